// round 2
// baseline (speedup 1.0000x reference)
#include <cuda_runtime.h>

#define HIDDEN 768
#define NHEADS 12
#define DEPTH  64
#define BATCH  2
#define SEQ    2048
#define MTOT   (BATCH*SEQ)                       /* 4096 */
#define OUT_ELEMS  ((size_t)MTOT*HIDDEN)         /* 3,145,728  */
#define ATTN_ELEMS ((size_t)BATCH*NHEADS*SEQ*SEQ)/* 100,663,296 */

// Scratch (allocation-free per harness rules). 256B-aligned: these are accessed
// through float4, and plain float globals are not guaranteed 16B alignment.
__device__ __align__(256) float g_Q[MTOT*HIDDEN];      // [B,H,S,D]
__device__ __align__(256) float g_K[MTOT*HIDDEN];      // [B,H,S,D]
__device__ __align__(256) float g_V[MTOT*HIDDEN];      // [B,H,S,D]
__device__ __align__(256) float g_ctx[MTOT*HIDDEN];    // [B,S,H*D]
__device__ __align__(256) float g_scores[ATTN_ELEMS];  // fallback staging if attn not exposed
__device__ __align__(256) float g_outsc[MTOT*HIDDEN];  // fallback out if attn-only output

// ---------------------------------------------------------------------------
// Fused QKV projection:  Y = X @ W^T + b, stored to [B,H,S,D]
// 64x64 tile, 256 threads, 4x4 micro-tile, K-chunks of 16.
// ---------------------------------------------------------------------------
__global__ __launch_bounds__(256) void qkv_proj_kernel(
    const float* __restrict__ qin, const float* __restrict__ kin, const float* __restrict__ vin,
    const float* __restrict__ Wq, const float* __restrict__ bq,
    const float* __restrict__ Wk, const float* __restrict__ bk,
    const float* __restrict__ Wv, const float* __restrict__ bv)
{
    const int z = blockIdx.z;
    const float* X    = (z == 0) ? qin : (z == 1) ? kin : vin;
    const float* W    = (z == 0) ? Wq  : (z == 1) ? Wk  : Wv;
    const float* bias = (z == 0) ? bq  : (z == 1) ? bk  : bv;
    float*       Y    = (z == 0) ? g_Q : (z == 1) ? g_K : g_V;

    const int m0 = blockIdx.y * 64;
    const int n0 = blockIdx.x * 64;

    __shared__ float As[16][68];   // k-major (transposed) for float4 reads
    __shared__ float Bs[16][68];

    const int t  = threadIdx.x;
    const int tx = t & 15;
    const int ty = t >> 4;

    float acc[4][4];
    #pragma unroll
    for (int i = 0; i < 4; i++)
        #pragma unroll
        for (int j = 0; j < 4; j++) acc[i][j] = 0.0f;

    for (int kk0 = 0; kk0 < HIDDEN; kk0 += 16) {
        #pragma unroll
        for (int i = 0; i < 4; i++) {
            int lin = t + i * 256;
            int r = lin >> 4, c = lin & 15;
            As[c][r] = X[(m0 + r) * HIDDEN + kk0 + c];
            Bs[c][r] = W[(n0 + r) * HIDDEN + kk0 + c];
        }
        __syncthreads();
        #pragma unroll
        for (int c = 0; c < 16; c++) {
            float4 a = *(const float4*)&As[c][ty * 4];
            float4 b = *(const float4*)&Bs[c][tx * 4];
            acc[0][0] += a.x * b.x; acc[0][1] += a.x * b.y; acc[0][2] += a.x * b.z; acc[0][3] += a.x * b.w;
            acc[1][0] += a.y * b.x; acc[1][1] += a.y * b.y; acc[1][2] += a.y * b.z; acc[1][3] += a.y * b.w;
            acc[2][0] += a.z * b.x; acc[2][1] += a.z * b.y; acc[2][2] += a.z * b.z; acc[2][3] += a.z * b.w;
            acc[3][0] += a.w * b.x; acc[3][1] += a.w * b.y; acc[3][2] += a.w * b.z; acc[3][3] += a.w * b.w;
        }
        __syncthreads();
    }

    // n-tile == one head (64 == DEPTH)
    const int h  = n0 / DEPTH;
    const int nb = n0 + tx * 4;
    #pragma unroll
    for (int i = 0; i < 4; i++) {
        int m  = m0 + ty * 4 + i;
        int bb = m >> 11;            // / SEQ
        int s  = m & (SEQ - 1);
        float4 o;
        o.x = acc[i][0] + bias[nb + 0];
        o.y = acc[i][1] + bias[nb + 1];
        o.z = acc[i][2] + bias[nb + 2];
        o.w = acc[i][3] + bias[nb + 3];
        *(float4*)&Y[(((size_t)(bb * NHEADS + h) * SEQ) + s) * DEPTH + tx * 4] = o;
    }
}

// ---------------------------------------------------------------------------
// Attention: one block per (bh, 64-query tile), 256 threads.
// Pass A: S = scale * Q K^T, write raw scores to attn buffer (staging),
//         online row max m and sum l via width-16 shuffles.
// Pass B: read raw back, p = exp(s-m)/l, write normalized probs (in place),
//         accumulate ctx = P V with register tiling.
// ---------------------------------------------------------------------------
__global__ __launch_bounds__(256) void attn_kernel(float* attn_out)
{
    float* attn = attn_out ? attn_out : g_scores;

    const int bh = blockIdx.y;          // 0..23
    const int q0 = blockIdx.x * 64;

    const float* Qh = g_Q + (size_t)bh * SEQ * DEPTH;
    const float* Kh = g_K + (size_t)bh * SEQ * DEPTH;
    const float* Vh = g_V + (size_t)bh * SEQ * DEPTH;
    float* attnp = attn + (size_t)bh * SEQ * SEQ + (size_t)q0 * SEQ;

    __shared__ float smA[64 * 68];      // Pass A: Q^T [d][q] ; Pass B: P [q][k]
    __shared__ float smB[64 * 68];      // Pass A: K^T [d][k] ; Pass B: V [k][d]

    const int t  = threadIdx.x;
    const int tx = t & 15;
    const int ty = t >> 4;
    const float scale = 0.125f;         // 1/sqrt(64)

    // Load Q tile transposed: smA[d][r] = Q[q0+r][d]
    #pragma unroll
    for (int i = 0; i < 16; i++) {
        int lin = t + i * 256;
        int r = lin >> 6, d = lin & 63;
        smA[d * 68 + r] = Qh[(size_t)(q0 + r) * DEPTH + d];
    }

    float m[4], l[4];
    #pragma unroll
    for (int i = 0; i < 4; i++) { m[i] = -1e30f; l[i] = 0.0f; }

    // ------------------ Pass A ------------------
    for (int k0 = 0; k0 < SEQ; k0 += 64) {
        __syncthreads();
        #pragma unroll
        for (int i = 0; i < 16; i++) {
            int lin = t + i * 256;
            int r = lin >> 6, d = lin & 63;
            smB[d * 68 + r] = Kh[(size_t)(k0 + r) * DEPTH + d];
        }
        __syncthreads();

        float sreg[4][4];
        #pragma unroll
        for (int i = 0; i < 4; i++)
            #pragma unroll
            for (int j = 0; j < 4; j++) sreg[i][j] = 0.0f;

        #pragma unroll
        for (int d = 0; d < 64; d++) {
            float4 a = *(const float4*)&smA[d * 68 + ty * 4];
            float4 b = *(const float4*)&smB[d * 68 + tx * 4];
            sreg[0][0] += a.x * b.x; sreg[0][1] += a.x * b.y; sreg[0][2] += a.x * b.z; sreg[0][3] += a.x * b.w;
            sreg[1][0] += a.y * b.x; sreg[1][1] += a.y * b.y; sreg[1][2] += a.y * b.z; sreg[1][3] += a.y * b.w;
            sreg[2][0] += a.z * b.x; sreg[2][1] += a.z * b.y; sreg[2][2] += a.z * b.z; sreg[2][3] += a.z * b.w;
            sreg[3][0] += a.w * b.x; sreg[3][1] += a.w * b.y; sreg[3][2] += a.w * b.z; sreg[3][3] += a.w * b.w;
        }

        #pragma unroll
        for (int i = 0; i < 4; i++) {
            float s0 = sreg[i][0] * scale, s1 = sreg[i][1] * scale;
            float s2 = sreg[i][2] * scale, s3 = sreg[i][3] * scale;
            float4 o; o.x = s0; o.y = s1; o.z = s2; o.w = s3;
            *(float4*)&attnp[(size_t)(ty * 4 + i) * SEQ + k0 + tx * 4] = o;  // raw staging

            float mloc = fmaxf(fmaxf(s0, s1), fmaxf(s2, s3));
            #pragma unroll
            for (int off = 1; off < 16; off <<= 1)
                mloc = fmaxf(mloc, __shfl_xor_sync(0xffffffffu, mloc, off, 16));

            float mnew = fmaxf(m[i], mloc);
            float se = __expf(s0 - mnew) + __expf(s1 - mnew) +
                       __expf(s2 - mnew) + __expf(s3 - mnew);
            #pragma unroll
            for (int off = 1; off < 16; off <<= 1)
                se += __shfl_xor_sync(0xffffffffu, se, off, 16);

            l[i] = l[i] * __expf(m[i] - mnew) + se;
            m[i] = mnew;
        }
    }

    float invl[4];
    #pragma unroll
    for (int i = 0; i < 4; i++) invl[i] = 1.0f / l[i];

    // ------------------ Pass B ------------------
    float ctx[4][4];
    #pragma unroll
    for (int i = 0; i < 4; i++)
        #pragma unroll
        for (int j = 0; j < 4; j++) ctx[i][j] = 0.0f;

    for (int k0 = 0; k0 < SEQ; k0 += 64) {
        __syncthreads();
        // V tile: smB[k][d]
        #pragma unroll
        for (int i = 0; i < 16; i++) {
            int lin = t + i * 256;
            int r = lin >> 6, d = lin & 63;
            smB[r * 68 + d] = Vh[(size_t)(k0 + r) * DEPTH + d];
        }
        // normalize raw scores, write final probs (in place), stage P in smA[q][k]
        #pragma unroll
        for (int i = 0; i < 4; i++) {
            float4 raw = *(const float4*)&attnp[(size_t)(ty * 4 + i) * SEQ + k0 + tx * 4];
            float4 p;
            p.x = __expf(raw.x - m[i]) * invl[i];
            p.y = __expf(raw.y - m[i]) * invl[i];
            p.z = __expf(raw.z - m[i]) * invl[i];
            p.w = __expf(raw.w - m[i]) * invl[i];
            *(float4*)&attnp[(size_t)(ty * 4 + i) * SEQ + k0 + tx * 4] = p;
            *(float4*)&smA[(ty * 4 + i) * 68 + tx * 4] = p;
        }
        __syncthreads();

        #pragma unroll
        for (int kk = 0; kk < 64; kk++) {
            float a0 = smA[(ty * 4 + 0) * 68 + kk];
            float a1 = smA[(ty * 4 + 1) * 68 + kk];
            float a2 = smA[(ty * 4 + 2) * 68 + kk];
            float a3 = smA[(ty * 4 + 3) * 68 + kk];
            float4 b = *(const float4*)&smB[kk * 68 + tx * 4];
            ctx[0][0] += a0 * b.x; ctx[0][1] += a0 * b.y; ctx[0][2] += a0 * b.z; ctx[0][3] += a0 * b.w;
            ctx[1][0] += a1 * b.x; ctx[1][1] += a1 * b.y; ctx[1][2] += a1 * b.z; ctx[1][3] += a1 * b.w;
            ctx[2][0] += a2 * b.x; ctx[2][1] += a2 * b.y; ctx[2][2] += a2 * b.z; ctx[2][3] += a2 * b.w;
            ctx[3][0] += a3 * b.x; ctx[3][1] += a3 * b.y; ctx[3][2] += a3 * b.z; ctx[3][3] += a3 * b.w;
        }
    }

    // store ctx to [B, S, H*D]
    const int bb = bh / NHEADS;
    const int h  = bh % NHEADS;
    #pragma unroll
    for (int i = 0; i < 4; i++) {
        int s = q0 + ty * 4 + i;
        float4 o;
        o.x = ctx[i][0]; o.y = ctx[i][1]; o.z = ctx[i][2]; o.w = ctx[i][3];
        *(float4*)&g_ctx[((size_t)(bb * SEQ + s)) * HIDDEN + h * DEPTH + tx * 4] = o;
    }
}

// ---------------------------------------------------------------------------
// Output projection: out = ctx @ Wo^T + bo
// ---------------------------------------------------------------------------
__global__ __launch_bounds__(256) void out_proj_kernel(
    const float* __restrict__ Wo, const float* __restrict__ bo, float* out)
{
    float* O = out ? out : g_outsc;

    const int m0 = blockIdx.y * 64;
    const int n0 = blockIdx.x * 64;

    __shared__ float As[16][68];
    __shared__ float Bs[16][68];

    const int t  = threadIdx.x;
    const int tx = t & 15;
    const int ty = t >> 4;

    float acc[4][4];
    #pragma unroll
    for (int i = 0; i < 4; i++)
        #pragma unroll
        for (int j = 0; j < 4; j++) acc[i][j] = 0.0f;

    for (int kk0 = 0; kk0 < HIDDEN; kk0 += 16) {
        #pragma unroll
        for (int i = 0; i < 4; i++) {
            int lin = t + i * 256;
            int r = lin >> 4, c = lin & 15;
            As[c][r] = g_ctx[(size_t)(m0 + r) * HIDDEN + kk0 + c];
            Bs[c][r] = Wo[(size_t)(n0 + r) * HIDDEN + kk0 + c];
        }
        __syncthreads();
        #pragma unroll
        for (int c = 0; c < 16; c++) {
            float4 a = *(const float4*)&As[c][ty * 4];
            float4 b = *(const float4*)&Bs[c][tx * 4];
            acc[0][0] += a.x * b.x; acc[0][1] += a.x * b.y; acc[0][2] += a.x * b.z; acc[0][3] += a.x * b.w;
            acc[1][0] += a.y * b.x; acc[1][1] += a.y * b.y; acc[1][2] += a.y * b.z; acc[1][3] += a.y * b.w;
            acc[2][0] += a.z * b.x; acc[2][1] += a.z * b.y; acc[2][2] += a.z * b.z; acc[2][3] += a.z * b.w;
            acc[3][0] += a.w * b.x; acc[3][1] += a.w * b.y; acc[3][2] += a.w * b.z; acc[3][3] += a.w * b.w;
        }
        __syncthreads();
    }

    const int nb = n0 + tx * 4;
    #pragma unroll
    for (int i = 0; i < 4; i++) {
        int mrow = m0 + ty * 4 + i;
        float4 o;
        o.x = acc[i][0] + bo[nb + 0];
        o.y = acc[i][1] + bo[nb + 1];
        o.z = acc[i][2] + bo[nb + 2];
        o.w = acc[i][3] + bo[nb + 3];
        *(float4*)&O[(size_t)mrow * HIDDEN + nb] = o;
    }
}

// ---------------------------------------------------------------------------
extern "C" void kernel_launch(void* const* d_in, const int* in_sizes, int n_in,
                              void* d_out, int out_size)
{
    const float* q  = (const float*)d_in[0];
    const float* k  = (const float*)d_in[1];
    const float* v  = (const float*)d_in[2];
    const float* Wq = (const float*)d_in[3];
    const float* bq = (const float*)d_in[4];
    const float* Wk = (const float*)d_in[5];
    const float* bk = (const float*)d_in[6];
    const float* Wv = (const float*)d_in[7];
    const float* bv = (const float*)d_in[8];
    const float* Wo = (const float*)d_in[9];
    const float* bo = (const float*)d_in[10];

    // Output layout: reference returns (out, attn); handle all flattening cases.
    float* outp  = nullptr;   // nullptr -> scratch
    float* attnp = nullptr;   // nullptr -> scratch
    size_t os = (size_t)out_size;
    if (os >= OUT_ELEMS + ATTN_ELEMS) {
        outp  = (float*)d_out;
        attnp = (float*)d_out + OUT_ELEMS;
    } else if (os >= ATTN_ELEMS) {
        attnp = (float*)d_out;            // attn only
    } else {
        outp  = (float*)d_out;            // out only
    }

    qkv_proj_kernel<<<dim3(HIDDEN / 64, MTOT / 64, 3), 256>>>(
        q, k, v, Wq, bq, Wk, bk, Wv, bv);
    attn_kernel<<<dim3(SEQ / 64, BATCH * NHEADS), 256>>>(attnp);
    out_proj_kernel<<<dim3(HIDDEN / 64, MTOT / 64), 256>>>(Wo, bo, outp);
}

// round 3
// speedup vs baseline: 1.4604x; 1.4604x over previous
#include <cuda_runtime.h>
#include <cuda_bf16.h>
#include <cstdint>

#define HIDDEN 768
#define NHEADS 12
#define DEPTH  64
#define BATCH  2
#define SEQ    2048
#define MTOT   (BATCH*SEQ)                        /* 4096 */
#define BH     (BATCH*NHEADS)                     /* 24   */
#define OUT_ELEMS  ((size_t)MTOT*HIDDEN)          /* 3,145,728   */
#define ATTN_ELEMS ((size_t)BH*SEQ*SEQ)           /* 100,663,296 */

// Scratch (allocation-free). Q/K/V stored as split bf16 (hi + lo ~ fp32 accuracy).
__device__ __align__(256) __nv_bfloat16 g_Qh[BH*SEQ*DEPTH];
__device__ __align__(256) __nv_bfloat16 g_Ql[BH*SEQ*DEPTH];
__device__ __align__(256) __nv_bfloat16 g_Kh[BH*SEQ*DEPTH];
__device__ __align__(256) __nv_bfloat16 g_Kl[BH*SEQ*DEPTH];
__device__ __align__(256) __nv_bfloat16 g_Vh[BH*SEQ*DEPTH];
__device__ __align__(256) __nv_bfloat16 g_Vl[BH*SEQ*DEPTH];
__device__ __align__(256) float g_ctx[MTOT*HIDDEN];
__device__ __align__(256) float g_scores[ATTN_ELEMS];  // staging fallback
__device__ __align__(256) float g_outsc[MTOT*HIDDEN];  // out fallback

// ---------------------------------------------------------------------------
// helpers
// ---------------------------------------------------------------------------
__device__ __forceinline__ void splitbf(float x, __nv_bfloat16& h, __nv_bfloat16& l) {
    h = __float2bfloat16(x);
    l = __float2bfloat16(x - __bfloat162float(h));
}

// XOR swizzle for 64-half rows: conflict-free ldmatrix + stores.
__device__ __forceinline__ int swz(int r, int c) {
    return (r << 6) | (c ^ ((r & 7) << 3));
}

__device__ __forceinline__ void ldsm4(uint32_t* r, uint32_t addr) {
    asm volatile("ldmatrix.sync.aligned.m8n8.x4.shared.b16 {%0,%1,%2,%3}, [%4];\n"
                 : "=r"(r[0]), "=r"(r[1]), "=r"(r[2]), "=r"(r[3]) : "r"(addr));
}
__device__ __forceinline__ void ldsm4t(uint32_t* r, uint32_t addr) {
    asm volatile("ldmatrix.sync.aligned.m8n8.x4.trans.shared.b16 {%0,%1,%2,%3}, [%4];\n"
                 : "=r"(r[0]), "=r"(r[1]), "=r"(r[2]), "=r"(r[3]) : "r"(addr));
}
__device__ __forceinline__ void mma16816(float* c, const uint32_t* a, uint32_t b0, uint32_t b1) {
    asm volatile(
        "mma.sync.aligned.m16n8k16.row.col.f32.bf16.bf16.f32 "
        "{%0,%1,%2,%3}, {%4,%5,%6,%7}, {%8,%9}, {%0,%1,%2,%3};\n"
        : "+f"(c[0]), "+f"(c[1]), "+f"(c[2]), "+f"(c[3])
        : "r"(a[0]), "r"(a[1]), "r"(a[2]), "r"(a[3]), "r"(b0), "r"(b1));
}

// A-fragment (row-major [m][k] tile) / B-pair (n-major [n][k] tile) ldmatrix x4.
// lane -> (row0 + (l&7) + ((l>>3)&1)*8, kc + ((l>>4)<<3))
__device__ __forceinline__ void ldmA(uint32_t base_u, int row0, int kc, int lane, uint32_t* r) {
    int row = row0 + (lane & 7) + ((lane >> 3) & 1) * 8;
    int col = kc + ((lane >> 4) << 3);
    ldsm4(r, base_u + (swz(row, col) << 1));
}
// V (k-major [k][n] tile) trans ldmatrix x4 -> frag nf {r0,r1}, nf+1 {r2,r3}
__device__ __forceinline__ void ldmV(uint32_t base_u, int kc, int n0, int lane, uint32_t* r) {
    int row = kc + (lane & 7) + ((lane >> 3) & 1) * 8;
    int col = n0 + ((lane >> 4) << 3);
    ldsm4t(r, base_u + (swz(row, col) << 1));
}

// ---------------------------------------------------------------------------
// QKV projection: Y = X @ W^T + b -> split bf16 [bh][s][d]
// block: 256 thr (8 warps), tile 128(m) x 64(n == one head), K-chunks of 64
// ---------------------------------------------------------------------------
__global__ __launch_bounds__(256) void qkv_proj_bf16(
    const float* __restrict__ qin, const float* __restrict__ kin, const float* __restrict__ vin,
    const float* __restrict__ Wq, const float* __restrict__ bq,
    const float* __restrict__ Wk, const float* __restrict__ bk,
    const float* __restrict__ Wv, const float* __restrict__ bv)
{
    const int z = blockIdx.z;
    const float* X    = (z == 0) ? qin : (z == 1) ? kin : vin;
    const float* W    = (z == 0) ? Wq  : (z == 1) ? Wk  : Wv;
    const float* bias = (z == 0) ? bq  : (z == 1) ? bk  : bv;
    __nv_bfloat16* Yh = (z == 0) ? g_Qh : (z == 1) ? g_Kh : g_Vh;
    __nv_bfloat16* Yl = (z == 0) ? g_Ql : (z == 1) ? g_Kl : g_Vl;

    const int m0 = blockIdx.y * 128;
    const int h  = blockIdx.x;          // head == n-tile
    const int n0g = h * 64;

    __shared__ __nv_bfloat16 sAh[128 * 64], sAl[128 * 64];
    __shared__ __nv_bfloat16 sBh[64 * 64],  sBl[64 * 64];

    const int t = threadIdx.x, lane = t & 31, w = t >> 5;
    const uint32_t sAh_u = (uint32_t)__cvta_generic_to_shared(sAh);
    const uint32_t sAl_u = (uint32_t)__cvta_generic_to_shared(sAl);
    const uint32_t sBh_u = (uint32_t)__cvta_generic_to_shared(sBh);
    const uint32_t sBl_u = (uint32_t)__cvta_generic_to_shared(sBl);

    float acc[8][4];
    #pragma unroll
    for (int i = 0; i < 8; i++)
        #pragma unroll
        for (int j = 0; j < 4; j++) acc[i][j] = 0.0f;

    const int r0 = t >> 4, c4 = t & 15;
    for (int kk = 0; kk < HIDDEN; kk += 64) {
        __syncthreads();
        #pragma unroll
        for (int i = 0; i < 8; i++) {
            int r = r0 + i * 16;
            float4 xv = *(const float4*)&X[(size_t)(m0 + r) * HIDDEN + kk + c4 * 4];
            __nv_bfloat16 h0, l0, h1, l1, h2, l2, h3, l3;
            splitbf(xv.x, h0, l0); splitbf(xv.y, h1, l1);
            splitbf(xv.z, h2, l2); splitbf(xv.w, h3, l3);
            int o = swz(r, c4 * 4);
            *(__nv_bfloat162*)&sAh[o]     = __nv_bfloat162{h0, h1};
            *(__nv_bfloat162*)&sAh[o + 2] = __nv_bfloat162{h2, h3};
            *(__nv_bfloat162*)&sAl[o]     = __nv_bfloat162{l0, l1};
            *(__nv_bfloat162*)&sAl[o + 2] = __nv_bfloat162{l2, l3};
        }
        #pragma unroll
        for (int i = 0; i < 4; i++) {
            int r = r0 + i * 16;
            float4 wv = *(const float4*)&W[(size_t)(n0g + r) * HIDDEN + kk + c4 * 4];
            __nv_bfloat16 h0, l0, h1, l1, h2, l2, h3, l3;
            splitbf(wv.x, h0, l0); splitbf(wv.y, h1, l1);
            splitbf(wv.z, h2, l2); splitbf(wv.w, h3, l3);
            int o = swz(r, c4 * 4);
            *(__nv_bfloat162*)&sBh[o]     = __nv_bfloat162{h0, h1};
            *(__nv_bfloat162*)&sBh[o + 2] = __nv_bfloat162{h2, h3};
            *(__nv_bfloat162*)&sBl[o]     = __nv_bfloat162{l0, l1};
            *(__nv_bfloat162*)&sBl[o + 2] = __nv_bfloat162{l2, l3};
        }
        __syncthreads();

        #pragma unroll
        for (int c = 0; c < 4; c++) {
            uint32_t ah[4], al[4];
            ldmA(sAh_u, w * 16, c * 16, lane, ah);
            ldmA(sAl_u, w * 16, c * 16, lane, al);
            #pragma unroll
            for (int np = 0; np < 4; np++) {
                uint32_t bh_[4], bl_[4];
                ldmA(sBh_u, np * 16, c * 16, lane, bh_);
                ldmA(sBl_u, np * 16, c * 16, lane, bl_);
                mma16816(acc[2 * np],     ah, bh_[0], bh_[2]);
                mma16816(acc[2 * np],     ah, bl_[0], bl_[2]);
                mma16816(acc[2 * np],     al, bh_[0], bh_[2]);
                mma16816(acc[2 * np + 1], ah, bh_[1], bh_[3]);
                mma16816(acc[2 * np + 1], ah, bl_[1], bl_[3]);
                mma16816(acc[2 * np + 1], al, bh_[1], bh_[3]);
            }
        }
    }

    const int g = lane >> 2, tq = lane & 3;
    #pragma unroll
    for (int nf = 0; nf < 8; nf++) {
        int d  = nf * 8 + tq * 2;        // within head
        float b0v = bias[n0g + d], b1v = bias[n0g + d + 1];
        #pragma unroll
        for (int rr = 0; rr < 2; rr++) {
            int m  = m0 + w * 16 + g + rr * 8;
            int bb = m >> 11, s = m & (SEQ - 1);
            size_t oidx = ((size_t)(bb * NHEADS + h) * SEQ + s) * DEPTH + d;
            float y0 = acc[nf][rr * 2 + 0] + b0v;
            float y1 = acc[nf][rr * 2 + 1] + b1v;
            __nv_bfloat16 h0, l0, h1, l1;
            splitbf(y0, h0, l0); splitbf(y1, h1, l1);
            *(__nv_bfloat162*)&Yh[oidx] = __nv_bfloat162{h0, h1};
            *(__nv_bfloat162*)&Yl[oidx] = __nv_bfloat162{l0, l1};
        }
    }
}

// ---------------------------------------------------------------------------
// Attention: block = (bh, 128-query tile), 256 thr (8 warps, 16 rows each).
// Pass A: scores via split-bf16 MMA -> fp32 scaled raw, staged to attn buffer,
//         online (m,l) per row (warp-local, quad shuffles).
// Pass B: reload raw, p = exp(s-m)/l -> final probs (in place) + P·V via MMA.
// ---------------------------------------------------------------------------
__global__ __launch_bounds__(256) void attn_bf16(float* attn_out)
{
    float* attn = attn_out ? attn_out : g_scores;

    const int bh = blockIdx.y;
    const int q0 = blockIdx.x * 128;

    const __nv_bfloat16* Qh = g_Qh + (size_t)bh * SEQ * DEPTH;
    const __nv_bfloat16* Ql = g_Ql + (size_t)bh * SEQ * DEPTH;
    const __nv_bfloat16* Kh = g_Kh + (size_t)bh * SEQ * DEPTH;
    const __nv_bfloat16* Kl = g_Kl + (size_t)bh * SEQ * DEPTH;
    const __nv_bfloat16* Vh = g_Vh + (size_t)bh * SEQ * DEPTH;
    const __nv_bfloat16* Vl = g_Vl + (size_t)bh * SEQ * DEPTH;
    float* attnp = attn + (size_t)bh * SEQ * SEQ + (size_t)q0 * SEQ;

    __shared__ __nv_bfloat16 sAh[128 * 64], sAl[128 * 64];   // Q, later P
    __shared__ __nv_bfloat16 sBh[64 * 64],  sBl[64 * 64];    // K, later V

    const int t = threadIdx.x, lane = t & 31, w = t >> 5;
    const int g = lane >> 2, tq = lane & 3;
    const uint32_t sAh_u = (uint32_t)__cvta_generic_to_shared(sAh);
    const uint32_t sAl_u = (uint32_t)__cvta_generic_to_shared(sAl);
    const uint32_t sBh_u = (uint32_t)__cvta_generic_to_shared(sBh);
    const uint32_t sBl_u = (uint32_t)__cvta_generic_to_shared(sBl);

    // ---- load Q tile (128 x 64 halves, hi+lo) ----
    {
        const int r0 = t >> 4, c = t & 15;
        #pragma unroll
        for (int i = 0; i < 8; i++) {
            int r = r0 + i * 16;
            uint2 hv = *(const uint2*)&Qh[(size_t)(q0 + r) * DEPTH + c * 4];
            uint2 lv = *(const uint2*)&Ql[(size_t)(q0 + r) * DEPTH + c * 4];
            int o = swz(r, c * 4);
            *(uint32_t*)&sAh[o] = hv.x; *(uint32_t*)&sAh[o + 2] = hv.y;
            *(uint32_t*)&sAl[o] = lv.x; *(uint32_t*)&sAl[o + 2] = lv.y;
        }
    }
    __syncthreads();

    // preload Q fragments (resident for pass A)
    uint32_t aQh[4][4], aQl[4][4];
    #pragma unroll
    for (int c = 0; c < 4; c++) {
        ldmA(sAh_u, w * 16, c * 16, lane, aQh[c]);
        ldmA(sAl_u, w * 16, c * 16, lane, aQl[c]);
    }

    float mA = -1e30f, mB = -1e30f, lA = 0.0f, lB = 0.0f;
    const int rowA = w * 16 + g, rowB = rowA + 8;

    // ------------------ Pass A ------------------
    for (int k0 = 0; k0 < SEQ; k0 += 64) {
        __syncthreads();
        {
            const int r0 = t >> 4, c = t & 15;
            #pragma unroll
            for (int i = 0; i < 4; i++) {
                int r = r0 + i * 16;
                uint2 hv = *(const uint2*)&Kh[(size_t)(k0 + r) * DEPTH + c * 4];
                uint2 lv = *(const uint2*)&Kl[(size_t)(k0 + r) * DEPTH + c * 4];
                int o = swz(r, c * 4);
                *(uint32_t*)&sBh[o] = hv.x; *(uint32_t*)&sBh[o + 2] = hv.y;
                *(uint32_t*)&sBl[o] = lv.x; *(uint32_t*)&sBl[o + 2] = lv.y;
            }
        }
        __syncthreads();

        float sc[8][4];
        #pragma unroll
        for (int i = 0; i < 8; i++)
            #pragma unroll
            for (int j = 0; j < 4; j++) sc[i][j] = 0.0f;

        #pragma unroll
        for (int c = 0; c < 4; c++) {
            #pragma unroll
            for (int np = 0; np < 4; np++) {
                uint32_t bh_[4], bl_[4];
                ldmA(sBh_u, np * 16, c * 16, lane, bh_);
                ldmA(sBl_u, np * 16, c * 16, lane, bl_);
                mma16816(sc[2 * np],     aQh[c], bh_[0], bh_[2]);
                mma16816(sc[2 * np],     aQh[c], bl_[0], bl_[2]);
                mma16816(sc[2 * np],     aQl[c], bh_[0], bh_[2]);
                mma16816(sc[2 * np + 1], aQh[c], bh_[1], bh_[3]);
                mma16816(sc[2 * np + 1], aQh[c], bl_[1], bl_[3]);
                mma16816(sc[2 * np + 1], aQl[c], bh_[1], bh_[3]);
            }
        }

        // scale, stage raw, online stats
        float mlocA = -1e30f, mlocB = -1e30f;
        #pragma unroll
        for (int nf = 0; nf < 8; nf++) {
            #pragma unroll
            for (int j = 0; j < 4; j++) sc[nf][j] *= 0.125f;
            mlocA = fmaxf(mlocA, fmaxf(sc[nf][0], sc[nf][1]));
            mlocB = fmaxf(mlocB, fmaxf(sc[nf][2], sc[nf][3]));
            *(float2*)&attnp[(size_t)rowA * SEQ + k0 + nf * 8 + tq * 2] = float2{sc[nf][0], sc[nf][1]};
            *(float2*)&attnp[(size_t)rowB * SEQ + k0 + nf * 8 + tq * 2] = float2{sc[nf][2], sc[nf][3]};
        }
        #pragma unroll
        for (int off = 1; off < 4; off <<= 1) {
            mlocA = fmaxf(mlocA, __shfl_xor_sync(0xffffffffu, mlocA, off));
            mlocB = fmaxf(mlocB, __shfl_xor_sync(0xffffffffu, mlocB, off));
        }
        float mnA = fmaxf(mA, mlocA), mnB = fmaxf(mB, mlocB);
        float sA = 0.0f, sB = 0.0f;
        #pragma unroll
        for (int nf = 0; nf < 8; nf++) {
            sA += __expf(sc[nf][0] - mnA) + __expf(sc[nf][1] - mnA);
            sB += __expf(sc[nf][2] - mnB) + __expf(sc[nf][3] - mnB);
        }
        #pragma unroll
        for (int off = 1; off < 4; off <<= 1) {
            sA += __shfl_xor_sync(0xffffffffu, sA, off);
            sB += __shfl_xor_sync(0xffffffffu, sB, off);
        }
        lA = lA * __expf(mA - mnA) + sA; mA = mnA;
        lB = lB * __expf(mB - mnB) + sB; mB = mnB;
    }

    const float ivA = 1.0f / lA, ivB = 1.0f / lB;

    // ------------------ Pass B ------------------
    float ctx[8][4];
    #pragma unroll
    for (int i = 0; i < 8; i++)
        #pragma unroll
        for (int j = 0; j < 4; j++) ctx[i][j] = 0.0f;

    for (int k0 = 0; k0 < SEQ; k0 += 64) {
        __syncthreads();
        {
            const int r0 = t >> 4, c = t & 15;
            #pragma unroll
            for (int i = 0; i < 4; i++) {
                int r = r0 + i * 16;
                uint2 hv = *(const uint2*)&Vh[(size_t)(k0 + r) * DEPTH + c * 4];
                uint2 lv = *(const uint2*)&Vl[(size_t)(k0 + r) * DEPTH + c * 4];
                int o = swz(r, c * 4);
                *(uint32_t*)&sBh[o] = hv.x; *(uint32_t*)&sBh[o + 2] = hv.y;
                *(uint32_t*)&sBl[o] = lv.x; *(uint32_t*)&sBl[o + 2] = lv.y;
            }
        }
        // p = exp(raw - m)/l : final probs in place + split into sP (reuses sA)
        #pragma unroll
        for (int nf = 0; nf < 8; nf++) {
            int col = nf * 8 + tq * 2;
            float2 ra = *(const float2*)&attnp[(size_t)rowA * SEQ + k0 + col];
            float2 rb = *(const float2*)&attnp[(size_t)rowB * SEQ + k0 + col];
            float p0 = __expf(ra.x - mA) * ivA, p1 = __expf(ra.y - mA) * ivA;
            float p2 = __expf(rb.x - mB) * ivB, p3 = __expf(rb.y - mB) * ivB;
            *(float2*)&attnp[(size_t)rowA * SEQ + k0 + col] = float2{p0, p1};
            *(float2*)&attnp[(size_t)rowB * SEQ + k0 + col] = float2{p2, p3};
            __nv_bfloat16 h0, l0, h1, l1, h2, l2, h3, l3;
            splitbf(p0, h0, l0); splitbf(p1, h1, l1);
            splitbf(p2, h2, l2); splitbf(p3, h3, l3);
            *(__nv_bfloat162*)&sAh[swz(rowA, col)] = __nv_bfloat162{h0, h1};
            *(__nv_bfloat162*)&sAl[swz(rowA, col)] = __nv_bfloat162{l0, l1};
            *(__nv_bfloat162*)&sAh[swz(rowB, col)] = __nv_bfloat162{h2, h3};
            *(__nv_bfloat162*)&sAl[swz(rowB, col)] = __nv_bfloat162{l2, l3};
        }
        __syncthreads();

        #pragma unroll
        for (int c = 0; c < 4; c++) {
            uint32_t ah[4], al[4];
            ldmA(sAh_u, w * 16, c * 16, lane, ah);
            ldmA(sAl_u, w * 16, c * 16, lane, al);
            #pragma unroll
            for (int np = 0; np < 4; np++) {
                uint32_t bh_[4], bl_[4];
                ldmV(sBh_u, c * 16, np * 16, lane, bh_);
                ldmV(sBl_u, c * 16, np * 16, lane, bl_);
                mma16816(ctx[2 * np],     ah, bh_[0], bh_[1]);
                mma16816(ctx[2 * np],     ah, bl_[0], bl_[1]);
                mma16816(ctx[2 * np],     al, bh_[0], bh_[1]);
                mma16816(ctx[2 * np + 1], ah, bh_[2], bh_[3]);
                mma16816(ctx[2 * np + 1], ah, bl_[2], bl_[3]);
                mma16816(ctx[2 * np + 1], al, bh_[2], bh_[3]);
            }
        }
    }

    // store ctx -> [B, S, H*D] fp32
    const int bb = bh / NHEADS, h = bh % NHEADS;
    const int sA_ = q0 + rowA, sB_ = q0 + rowB;
    #pragma unroll
    for (int nf = 0; nf < 8; nf++) {
        int d = nf * 8 + tq * 2;
        *(float2*)&g_ctx[((size_t)(bb * SEQ + sA_)) * HIDDEN + h * DEPTH + d] = float2{ctx[nf][0], ctx[nf][1]};
        *(float2*)&g_ctx[((size_t)(bb * SEQ + sB_)) * HIDDEN + h * DEPTH + d] = float2{ctx[nf][2], ctx[nf][3]};
    }
}

// ---------------------------------------------------------------------------
// Output projection: out = ctx @ Wo^T + bo (fp32 in/out, split-bf16 MMA)
// ---------------------------------------------------------------------------
__global__ __launch_bounds__(256) void out_proj_bf16(
    const float* __restrict__ Wo, const float* __restrict__ bo, float* out)
{
    float* O = out ? out : g_outsc;

    const int m0 = blockIdx.y * 128;
    const int n0g = blockIdx.x * 64;

    __shared__ __nv_bfloat16 sAh[128 * 64], sAl[128 * 64];
    __shared__ __nv_bfloat16 sBh[64 * 64],  sBl[64 * 64];

    const int t = threadIdx.x, lane = t & 31, w = t >> 5;
    const uint32_t sAh_u = (uint32_t)__cvta_generic_to_shared(sAh);
    const uint32_t sAl_u = (uint32_t)__cvta_generic_to_shared(sAl);
    const uint32_t sBh_u = (uint32_t)__cvta_generic_to_shared(sBh);
    const uint32_t sBl_u = (uint32_t)__cvta_generic_to_shared(sBl);

    float acc[8][4];
    #pragma unroll
    for (int i = 0; i < 8; i++)
        #pragma unroll
        for (int j = 0; j < 4; j++) acc[i][j] = 0.0f;

    const int r0 = t >> 4, c4 = t & 15;
    for (int kk = 0; kk < HIDDEN; kk += 64) {
        __syncthreads();
        #pragma unroll
        for (int i = 0; i < 8; i++) {
            int r = r0 + i * 16;
            float4 xv = *(const float4*)&g_ctx[(size_t)(m0 + r) * HIDDEN + kk + c4 * 4];
            __nv_bfloat16 h0, l0, h1, l1, h2, l2, h3, l3;
            splitbf(xv.x, h0, l0); splitbf(xv.y, h1, l1);
            splitbf(xv.z, h2, l2); splitbf(xv.w, h3, l3);
            int o = swz(r, c4 * 4);
            *(__nv_bfloat162*)&sAh[o]     = __nv_bfloat162{h0, h1};
            *(__nv_bfloat162*)&sAh[o + 2] = __nv_bfloat162{h2, h3};
            *(__nv_bfloat162*)&sAl[o]     = __nv_bfloat162{l0, l1};
            *(__nv_bfloat162*)&sAl[o + 2] = __nv_bfloat162{l2, l3};
        }
        #pragma unroll
        for (int i = 0; i < 4; i++) {
            int r = r0 + i * 16;
            float4 wv = *(const float4*)&Wo[(size_t)(n0g + r) * HIDDEN + kk + c4 * 4];
            __nv_bfloat16 h0, l0, h1, l1, h2, l2, h3, l3;
            splitbf(wv.x, h0, l0); splitbf(wv.y, h1, l1);
            splitbf(wv.z, h2, l2); splitbf(wv.w, h3, l3);
            int o = swz(r, c4 * 4);
            *(__nv_bfloat162*)&sBh[o]     = __nv_bfloat162{h0, h1};
            *(__nv_bfloat162*)&sBh[o + 2] = __nv_bfloat162{h2, h3};
            *(__nv_bfloat162*)&sBl[o]     = __nv_bfloat162{l0, l1};
            *(__nv_bfloat162*)&sBl[o + 2] = __nv_bfloat162{l2, l3};
        }
        __syncthreads();

        #pragma unroll
        for (int c = 0; c < 4; c++) {
            uint32_t ah[4], al[4];
            ldmA(sAh_u, w * 16, c * 16, lane, ah);
            ldmA(sAl_u, w * 16, c * 16, lane, al);
            #pragma unroll
            for (int np = 0; np < 4; np++) {
                uint32_t bh_[4], bl_[4];
                ldmA(sBh_u, np * 16, c * 16, lane, bh_);
                ldmA(sBl_u, np * 16, c * 16, lane, bl_);
                mma16816(acc[2 * np],     ah, bh_[0], bh_[2]);
                mma16816(acc[2 * np],     ah, bl_[0], bl_[2]);
                mma16816(acc[2 * np],     al, bh_[0], bh_[2]);
                mma16816(acc[2 * np + 1], ah, bh_[1], bh_[3]);
                mma16816(acc[2 * np + 1], ah, bl_[1], bl_[3]);
                mma16816(acc[2 * np + 1], al, bh_[1], bh_[3]);
            }
        }
    }

    const int g = lane >> 2, tq = lane & 3;
    #pragma unroll
    for (int nf = 0; nf < 8; nf++) {
        int n = n0g + nf * 8 + tq * 2;
        float b0v = bo[n], b1v = bo[n + 1];
        #pragma unroll
        for (int rr = 0; rr < 2; rr++) {
            int m = m0 + w * 16 + g + rr * 8;
            *(float2*)&O[(size_t)m * HIDDEN + n] =
                float2{acc[nf][rr * 2 + 0] + b0v, acc[nf][rr * 2 + 1] + b1v};
        }
    }
}

// ---------------------------------------------------------------------------
extern "C" void kernel_launch(void* const* d_in, const int* in_sizes, int n_in,
                              void* d_out, int out_size)
{
    const float* q  = (const float*)d_in[0];
    const float* k  = (const float*)d_in[1];
    const float* v  = (const float*)d_in[2];
    const float* Wq = (const float*)d_in[3];
    const float* bq = (const float*)d_in[4];
    const float* Wk = (const float*)d_in[5];
    const float* bk = (const float*)d_in[6];
    const float* Wv = (const float*)d_in[7];
    const float* bv = (const float*)d_in[8];
    const float* Wo = (const float*)d_in[9];
    const float* bo = (const float*)d_in[10];

    float* outp  = nullptr;
    float* attnp = nullptr;
    size_t os = (size_t)out_size;
    if (os >= OUT_ELEMS + ATTN_ELEMS) {
        outp  = (float*)d_out;
        attnp = (float*)d_out + OUT_ELEMS;
    } else if (os >= ATTN_ELEMS) {
        attnp = (float*)d_out;
    } else {
        outp  = (float*)d_out;
    }

    qkv_proj_bf16<<<dim3(HIDDEN / 64, MTOT / 128, 3), 256>>>(
        q, k, v, Wq, bq, Wk, bk, Wv, bv);
    attn_bf16<<<dim3(SEQ / 128, BH), 256>>>(attnp);
    out_proj_bf16<<<dim3(HIDDEN / 64, MTOT / 128), 256>>>(Wo, bo, outp);
}